// round 1
// baseline (speedup 1.0000x reference)
#include <cuda_runtime.h>
#include <math.h>

#define N_NODES 50000
#define NUM_E   400000
#define ETOT    (NUM_E + N_NODES)   // 450000, self-loops appended
#define IN_C    128
#define HID     32
#define HEADS   8
#define F1      (HEADS * HID)       // 256
#define OUT_C   64
#define K_CL    16
#define NEG_SLOPE 0.2f
#define EPS_F   1e-16f

// ---------------- scratch (device globals; no runtime allocation) -----------
__device__ float g_h1[(size_t)N_NODES * F1];     // x@W1
__device__ float g_out1[(size_t)N_NODES * F1];   // layer1 aggregation, then ELU in place
__device__ float g_h2[(size_t)N_NODES * OUT_C];  // h_act@W2
__device__ float g_asrc1[N_NODES * HEADS];
__device__ float g_adst1[N_NODES * HEADS];
__device__ float g_den1[N_NODES * HEADS];
__device__ float g_ex1[(size_t)ETOT * HEADS];
__device__ float g_asrc2[N_NODES];
__device__ float g_adst2[N_NODES];
__device__ float g_den2[N_NODES];
__device__ float g_ex2[ETOT];

// ---------------- helpers ----------------------------------------------------
__device__ __forceinline__ void red_add4(float* p, float x, float y, float z, float w) {
    asm volatile("red.global.add.v4.f32 [%0], {%1,%2,%3,%4};"
                 :: "l"(p), "f"(x), "f"(y), "f"(z), "f"(w) : "memory");
}
__device__ __forceinline__ void red_add2(float* p, float x, float y) {
    asm volatile("red.global.add.v2.f32 [%0], {%1,%2};"
                 :: "l"(p), "f"(x), "f"(y) : "memory");
}
__device__ __forceinline__ float lrelu(float x) { return x > 0.f ? x : NEG_SLOPE * x; }

// ---------------- zero scratch + output emb region ---------------------------
__global__ void zero_scratch(float* __restrict__ emb) {
    size_t i = (size_t)blockIdx.x * blockDim.x + threadIdx.x;
    size_t stride = (size_t)gridDim.x * blockDim.x;
    for (size_t j = i; j < (size_t)N_NODES * F1; j += stride) g_out1[j] = 0.f;
    for (size_t j = i; j < (size_t)N_NODES * HEADS; j += stride) g_den1[j] = 0.f;
    for (size_t j = i; j < (size_t)N_NODES; j += stride) g_den2[j] = 0.f;
    for (size_t j = i; j < (size_t)N_NODES * OUT_C; j += stride) emb[j] = 0.f;
}

// ---------------- tiled SGEMM: C[M,Nc] = A[M,Kc] @ B[Kc,Nc] ------------------
// Nc % 64 == 0, Kc % 16 == 0 (true for all three uses). M guarded.
#define BM 64
#define BN 64
#define BK 16
__global__ __launch_bounds__(256) void sgemm64(
    const float* __restrict__ A, const float* __restrict__ B,
    float* __restrict__ C, int M, int Nc, int Kc)
{
    __shared__ float As[BK][BM + 1];
    __shared__ float Bs[BK][BN + 1];
    int tid = threadIdx.x;
    int tx = tid & 15, ty = tid >> 4;
    int rowA = blockIdx.y * BM, colB = blockIdx.x * BN;
    float acc[4][4] = {};
    for (int k0 = 0; k0 < Kc; k0 += BK) {
        #pragma unroll
        for (int i = 0; i < 4; i++) {
            int l = tid + i * 256;
            int m = l >> 4, kk = l & 15;        // A: coalesced along K
            float v = 0.f;
            if (rowA + m < M) v = A[(size_t)(rowA + m) * Kc + k0 + kk];
            As[kk][m] = v;
            int nn = l & 63, kb = l >> 6;        // B: coalesced along N
            Bs[kb][nn] = B[(size_t)(k0 + kb) * Nc + colB + nn];
        }
        __syncthreads();
        #pragma unroll
        for (int kk = 0; kk < BK; kk++) {
            float ra[4], rb[4];
            #pragma unroll
            for (int i = 0; i < 4; i++) ra[i] = As[kk][ty * 4 + i];
            #pragma unroll
            for (int j = 0; j < 4; j++) rb[j] = Bs[kk][tx * 4 + j];
            #pragma unroll
            for (int i = 0; i < 4; i++)
                #pragma unroll
                for (int j = 0; j < 4; j++) acc[i][j] += ra[i] * rb[j];
        }
        __syncthreads();
    }
    #pragma unroll
    for (int i = 0; i < 4; i++) {
        int r = rowA + ty * 4 + i;
        if (r < M) {
            #pragma unroll
            for (int j = 0; j < 4; j++)
                C[(size_t)r * Nc + colB + tx * 4 + j] = acc[i][j];
        }
    }
}

// ---------------- attention dot products -------------------------------------
__global__ void att1_kernel(const float* __restrict__ att_src, const float* __restrict__ att_dst) {
    int idx = blockIdx.x * blockDim.x + threadIdx.x;
    if (idx >= N_NODES * HEADS) return;
    int n = idx >> 3, h = idx & 7;
    const float4* hp = (const float4*)(g_h1 + (size_t)n * F1 + h * HID);
    const float4* as = (const float4*)(att_src + h * HID);
    const float4* ad = (const float4*)(att_dst + h * HID);
    float s = 0.f, d = 0.f;
    #pragma unroll
    for (int i = 0; i < 8; i++) {
        float4 hv = hp[i], a = as[i], b = ad[i];
        s += hv.x * a.x + hv.y * a.y + hv.z * a.z + hv.w * a.w;
        d += hv.x * b.x + hv.y * b.y + hv.z * b.z + hv.w * b.w;
    }
    g_asrc1[idx] = s;
    g_adst1[idx] = d;
}

__global__ void att2_kernel(const float* __restrict__ att_src, const float* __restrict__ att_dst) {
    int n = blockIdx.x * blockDim.x + threadIdx.x;
    if (n >= N_NODES) return;
    const float4* hp = (const float4*)(g_h2 + (size_t)n * OUT_C);
    const float4* as = (const float4*)att_src;
    const float4* ad = (const float4*)att_dst;
    float s = 0.f, d = 0.f;
    #pragma unroll
    for (int i = 0; i < 16; i++) {
        float4 hv = hp[i], a = as[i], b = ad[i];
        s += hv.x * a.x + hv.y * a.y + hv.z * a.z + hv.w * a.w;
        d += hv.x * b.x + hv.y * b.y + hv.z * b.z + hv.w * b.w;
    }
    g_asrc2[n] = s;
    g_adst2[n] = d;
}

// ---------------- layer-1 edge softmax (exp + denominator) -------------------
__global__ void edge_soft1(const int* __restrict__ ei) {
    int e = blockIdx.x * blockDim.x + threadIdx.x;
    if (e >= ETOT) return;
    int s, d;
    if (e < NUM_E) { s = ei[e]; d = ei[NUM_E + e]; } else { s = d = e - NUM_E; }
    const float4* ap = (const float4*)(g_asrc1 + (size_t)s * HEADS);
    const float4* bp = (const float4*)(g_adst1 + (size_t)d * HEADS);
    float4* exo = (float4*)(g_ex1 + (size_t)e * HEADS);
    float4 r[2];
    #pragma unroll
    for (int q = 0; q < 2; q++) {
        float4 a = ap[q], b = bp[q];
        r[q].x = __expf(lrelu(a.x + b.x));
        r[q].y = __expf(lrelu(a.y + b.y));
        r[q].z = __expf(lrelu(a.z + b.z));
        r[q].w = __expf(lrelu(a.w + b.w));
        exo[q] = r[q];
    }
    float* dp = g_den1 + (size_t)d * HEADS;
    red_add4(dp, r[0].x, r[0].y, r[0].z, r[0].w);
    red_add4(dp + 4, r[1].x, r[1].y, r[1].z, r[1].w);
}

// ---------------- layer-1 aggregation (warp per edge) ------------------------
__global__ __launch_bounds__(256) void edge_aggr1(const int* __restrict__ ei) {
    int e = blockIdx.x * (blockDim.x >> 5) + (threadIdx.x >> 5);
    if (e >= ETOT) return;
    int lane = threadIdx.x & 31;
    int s, d;
    if (e < NUM_E) { s = ei[e]; d = ei[NUM_E + e]; } else { s = d = e - NUM_E; }
    int head = lane >> 2;                      // lane covers elems [lane*8, lane*8+8) -> one head
    float a = g_ex1[(size_t)e * HEADS + head] / (g_den1[(size_t)d * HEADS + head] + EPS_F);
    const float4* hp = (const float4*)(g_h1 + (size_t)s * F1) + lane * 2;
    float4 v0 = hp[0], v1 = hp[1];
    float* op = g_out1 + (size_t)d * F1 + lane * 8;
    red_add4(op,     v0.x * a, v0.y * a, v0.z * a, v0.w * a);
    red_add4(op + 4, v1.x * a, v1.y * a, v1.z * a, v1.w * a);
}

// ---------------- ELU (+b1) in place on g_out1 -------------------------------
__global__ void elu_kernel(const float* __restrict__ b1) {
    size_t i = (size_t)blockIdx.x * blockDim.x + threadIdx.x;
    size_t total = (size_t)N_NODES * F1 / 4;
    size_t stride = (size_t)gridDim.x * blockDim.x;
    for (size_t j = i; j < total; j += stride) {
        float4 v = ((float4*)g_out1)[j];
        int col = (int)((j * 4) & (F1 - 1));
        v.x += b1[col];     v.y += b1[col + 1];
        v.z += b1[col + 2]; v.w += b1[col + 3];
        v.x = v.x > 0.f ? v.x : expm1f(v.x);
        v.y = v.y > 0.f ? v.y : expm1f(v.y);
        v.z = v.z > 0.f ? v.z : expm1f(v.z);
        v.w = v.w > 0.f ? v.w : expm1f(v.w);
        ((float4*)g_out1)[j] = v;
    }
}

// ---------------- layer-2 edge softmax ---------------------------------------
__global__ void edge_soft2(const int* __restrict__ ei) {
    int e = blockIdx.x * blockDim.x + threadIdx.x;
    if (e >= ETOT) return;
    int s, d;
    if (e < NUM_E) { s = ei[e]; d = ei[NUM_E + e]; } else { s = d = e - NUM_E; }
    float ex = __expf(lrelu(g_asrc2[s] + g_adst2[d]));
    g_ex2[e] = ex;
    atomicAdd(g_den2 + d, ex);
}

// ---------------- layer-2 aggregation (warp per edge, writes embeddings) -----
__global__ __launch_bounds__(256) void edge_aggr2(const int* __restrict__ ei, float* __restrict__ emb) {
    int e = blockIdx.x * (blockDim.x >> 5) + (threadIdx.x >> 5);
    if (e >= ETOT) return;
    int lane = threadIdx.x & 31;
    int s, d;
    if (e < NUM_E) { s = ei[e]; d = ei[NUM_E + e]; } else { s = d = e - NUM_E; }
    float a = g_ex2[e] / (g_den2[d] + EPS_F);
    float2 v = *(const float2*)(g_h2 + (size_t)s * OUT_C + lane * 2);
    red_add2(emb + (size_t)d * OUT_C + lane * 2, v.x * a, v.y * a);
}

// ---------------- add b2 to embeddings ---------------------------------------
__global__ void bias2_kernel(float* __restrict__ emb, const float* __restrict__ b2) {
    size_t i = (size_t)blockIdx.x * blockDim.x + threadIdx.x;
    if (i < (size_t)N_NODES * OUT_C) emb[i] += b2[i & (OUT_C - 1)];
}

// ---------------- fused MLP head + softmax -----------------------------------
__global__ __launch_bounds__(256) void mlp_kernel(
    const float* __restrict__ emb,
    const float* __restrict__ Wm1, const float* __restrict__ bm1,
    const float* __restrict__ Wm2, const float* __restrict__ bm2,
    float* __restrict__ s_out)
{
    __shared__ float sW1[OUT_C * 128];   // 32 KB
    __shared__ float sW2[128 * K_CL];    // 8 KB
    __shared__ float sb1[128];
    __shared__ float sb2[K_CL];
    __shared__ float sHid[8][128];
    __shared__ float sEmb[8][OUT_C];
    int tid = threadIdx.x;
    for (int i = tid; i < OUT_C * 128; i += 256) sW1[i] = Wm1[i];
    for (int i = tid; i < 128 * K_CL; i += 256) sW2[i] = Wm2[i];
    if (tid < 128) sb1[tid] = bm1[tid];
    if (tid < K_CL) sb2[tid] = bm2[tid];
    __syncthreads();
    int warp = tid >> 5, lane = tid & 31;
    int n = blockIdx.x * 8 + warp;
    if (n >= N_NODES) return;
    float2 e2 = *(const float2*)(emb + (size_t)n * OUT_C + lane * 2);
    sEmb[warp][lane * 2] = e2.x;
    sEmb[warp][lane * 2 + 1] = e2.y;
    __syncwarp();
    #pragma unroll
    for (int w = 0; w < 4; w++) {
        int j = lane + w * 32;
        float acc = sb1[j];
        #pragma unroll 8
        for (int c = 0; c < OUT_C; c++) acc += sEmb[warp][c] * sW1[c * 128 + j];
        sHid[warp][j] = fmaxf(acc, 0.f);
    }
    __syncwarp();
    if (lane < K_CL) {
        float lg = sb2[lane];
        #pragma unroll 16
        for (int k = 0; k < 128; k++) lg += sHid[warp][k] * sW2[k * K_CL + lane];
        float mx = lg;
        #pragma unroll
        for (int m = 8; m >= 1; m >>= 1)
            mx = fmaxf(mx, __shfl_xor_sync(0xffff, mx, m, 16));
        float ev = __expf(lg - mx);
        float sum = ev;
        #pragma unroll
        for (int m = 8; m >= 1; m >>= 1)
            sum += __shfl_xor_sync(0xffff, sum, m, 16);
        s_out[(size_t)n * K_CL + lane] = ev / sum;
    }
}

// ---------------- launch ------------------------------------------------------
extern "C" void kernel_launch(void* const* d_in, const int* in_sizes, int n_in,
                              void* d_out, int out_size) {
    const float* x        = (const float*)d_in[0];
    const int*   ei       = (const int*)d_in[1];     // [2, E]: src then dst
    const float* W1       = (const float*)d_in[2];
    const float* att_src1 = (const float*)d_in[3];
    const float* att_dst1 = (const float*)d_in[4];
    const float* b1       = (const float*)d_in[5];
    const float* W2       = (const float*)d_in[6];
    const float* att_src2 = (const float*)d_in[7];
    const float* att_dst2 = (const float*)d_in[8];
    const float* b2       = (const float*)d_in[9];
    const float* Wm1      = (const float*)d_in[10];
    const float* bm1      = (const float*)d_in[11];
    const float* Wm2      = (const float*)d_in[12];
    const float* bm2      = (const float*)d_in[13];

    float* s_out = (float*)d_out;                      // [N, 16]
    float* emb   = (float*)d_out + (size_t)N_NODES * K_CL;  // [N, 64]

    float *ph1, *pout1, *ph2;
    cudaGetSymbolAddress((void**)&ph1, g_h1);
    cudaGetSymbolAddress((void**)&pout1, g_out1);
    cudaGetSymbolAddress((void**)&ph2, g_h2);

    // 0. zero accumulators
    zero_scratch<<<4096, 256>>>(emb);

    // 1. h1 = x @ W1   [50000,128]x[128,256]
    {
        dim3 grid(F1 / BN, (N_NODES + BM - 1) / BM);
        sgemm64<<<grid, 256>>>(x, W1, ph1, N_NODES, F1, IN_C);
    }
    // 2. attention dots layer 1
    att1_kernel<<<(N_NODES * HEADS + 255) / 256, 256>>>(att_src1, att_dst1);
    // 3. edge softmax layer 1
    edge_soft1<<<(ETOT + 255) / 256, 256>>>(ei);
    // 4. edge aggregation layer 1 (warp/edge)
    edge_aggr1<<<(ETOT + 7) / 8, 256>>>(ei);
    // 5. ELU(+b1) in place
    elu_kernel<<<8192, 256>>>(b1);
    // 6. h2 = h_act @ W2  [50000,256]x[256,64]
    {
        dim3 grid(OUT_C / BN, (N_NODES + BM - 1) / BM);
        sgemm64<<<grid, 256>>>(pout1, W2, ph2, N_NODES, OUT_C, F1);
    }
    // 7. attention dots layer 2
    att2_kernel<<<(N_NODES + 255) / 256, 256>>>(att_src2, att_dst2);
    // 8. edge softmax layer 2
    edge_soft2<<<(ETOT + 255) / 256, 256>>>(ei);
    // 9. edge aggregation layer 2 -> embeddings
    edge_aggr2<<<(ETOT + 7) / 8, 256>>>(ei, emb);
    // 10. + b2
    bias2_kernel<<<(N_NODES * OUT_C + 255) / 256, 256>>>(emb, b2);
    // 11. MLP head + softmax -> s
    mlp_kernel<<<(N_NODES + 7) / 8, 256>>>(emb, Wm1, bm1, Wm2, bm2, s_out);
}

// round 4
// speedup vs baseline: 1.1113x; 1.1113x over previous
#include <cuda_runtime.h>
#include <math.h>

#define N_NODES 50000
#define NUM_E   400000
#define ETOT    (NUM_E + N_NODES)   // 450000, self-loops appended
#define IN_C    128
#define HID     32
#define HEADS   8
#define F1      (HEADS * HID)       // 256
#define OUT_C   64
#define K_CL    16
#define NEG_SLOPE 0.2f
#define EPS_F   1e-16f

// ---------------- scratch (device globals; no runtime allocation) -----------
__device__ float g_h1[(size_t)N_NODES * F1];     // x@W1
__device__ float g_out1[(size_t)N_NODES * F1];   // layer1 aggregation (init = b1)
__device__ float g_h2[(size_t)N_NODES * OUT_C];  // ELU(out1)@W2
__device__ float g_asrc1[N_NODES * HEADS];
__device__ float g_adst1[N_NODES * HEADS];
__device__ float g_den1[N_NODES * HEADS];
__device__ float g_ex1[(size_t)ETOT * HEADS];
__device__ float g_asrc2[N_NODES];
__device__ float g_adst2[N_NODES];
__device__ float g_den2[N_NODES];
__device__ float g_ex2[ETOT];

// ---------------- helpers ----------------------------------------------------
__device__ __forceinline__ void red_add4(float* p, float x, float y, float z, float w) {
    asm volatile("red.global.add.v4.f32 [%0], {%1,%2,%3,%4};"
                 :: "l"(p), "f"(x), "f"(y), "f"(z), "f"(w) : "memory");
}
__device__ __forceinline__ void red_add2(float* p, float x, float y) {
    asm volatile("red.global.add.v2.f32 [%0], {%1,%2};"
                 :: "l"(p), "f"(x), "f"(y) : "memory");
}
__device__ __forceinline__ float lrelu(float x) { return x > 0.f ? x : NEG_SLOPE * x; }
__device__ __forceinline__ float elu1(float x)  { return x > 0.f ? x : expm1f(x); }

// packed f32x2 FMA (sm_103a FFMA2)
__device__ __forceinline__ void ffma2(unsigned long long& acc, unsigned long long a, unsigned long long b) {
    asm("fma.rn.f32x2 %0, %1, %2, %0;" : "+l"(acc) : "l"(a), "l"(b));
}
__device__ __forceinline__ unsigned long long pack2(float x) {
    unsigned long long r; asm("mov.b64 %0, {%1, %1};" : "=l"(r) : "f"(x)); return r;
}
__device__ __forceinline__ void unpack2(unsigned long long v, float& lo, float& hi) {
    asm("mov.b64 {%0, %1}, %2;" : "=f"(lo), "=f"(hi) : "l"(v));
}

// ---------------- init: biases folded in, accumulators zeroed ----------------
__global__ void init_scratch(float* __restrict__ emb,
                             const float* __restrict__ b1,
                             const float* __restrict__ b2) {
    size_t i = (size_t)blockIdx.x * blockDim.x + threadIdx.x;
    size_t stride = (size_t)gridDim.x * blockDim.x;
    for (size_t j = i; j < (size_t)N_NODES * F1; j += stride) g_out1[j] = b1[j & (F1 - 1)];
    for (size_t j = i; j < (size_t)N_NODES * HEADS; j += stride) g_den1[j] = 0.f;
    for (size_t j = i; j < (size_t)N_NODES; j += stride) g_den2[j] = 0.f;
    for (size_t j = i; j < (size_t)N_NODES * OUT_C; j += stride) emb[j] = b2[j & (OUT_C - 1)];
}

// ---------------- f32x2 SGEMM: C[M,Nc] = act(A)[M,Kc] @ B[Kc,Nc] -------------
// BM=128, BK=16, 256 threads. TN = BN/16 outputs per thread column-wise.
// ELU_A: apply ELU to A elements during load (GEMM2 fusion).
#define BMg 128
#define BKg 16
template<int BN, int TN, bool ELU_A>
__global__ __launch_bounds__(256) void sgemm_f32x2(
    const float* __restrict__ A, const float* __restrict__ B,
    float* __restrict__ C, int M, int Nc, int Kc)
{
    __shared__ float As[BKg][BMg + 4];
    __shared__ float Bs[BKg][BN + 4];
    const int tid = threadIdx.x;
    const int tx = tid & 15, ty = tid >> 4;
    const int rowA = blockIdx.y * BMg;
    const int colB = blockIdx.x * BN;

    unsigned long long acc[8][TN / 2];
    #pragma unroll
    for (int i = 0; i < 8; i++)
        #pragma unroll
        for (int j = 0; j < TN / 2; j++) acc[i][j] = 0ULL;

    const int arow = tid >> 1;            // 0..127
    const int akq  = (tid & 1) * 4;       // 0 or 4

    for (int k0 = 0; k0 < Kc; k0 += BKg) {
        // load A tile (transposed into As[k][m])
        #pragma unroll
        for (int half = 0; half < 2; half++) {
            int kof = akq + half * 8;
            float4 v = make_float4(0.f, 0.f, 0.f, 0.f);
            if (rowA + arow < M)
                v = *(const float4*)&A[(size_t)(rowA + arow) * Kc + k0 + kof];
            if (ELU_A) { v.x = elu1(v.x); v.y = elu1(v.y); v.z = elu1(v.z); v.w = elu1(v.w); }
            As[kof + 0][arow] = v.x;
            As[kof + 1][arow] = v.y;
            As[kof + 2][arow] = v.z;
            As[kof + 3][arow] = v.w;
        }
        // load B tile (row-major)
        if (BN == 128) {
            int bc = (tid & 31) * 4, br = tid >> 5;     // 8 rows/pass
            #pragma unroll
            for (int pass = 0; pass < 2; pass++) {
                int r = br + pass * 8;
                float4 v = *(const float4*)&B[(size_t)(k0 + r) * Nc + colB + bc];
                *(float4*)&Bs[r][bc] = v;
            }
        } else {                                         // BN == 64
            int bc = (tid & 15) * 4, br = tid >> 4;      // 16 rows
            float4 v = *(const float4*)&B[(size_t)(k0 + br) * Nc + colB + bc];
            *(float4*)&Bs[br][bc] = v;
        }
        __syncthreads();

        #pragma unroll
        for (int kk = 0; kk < BKg; kk++) {
            unsigned long long rb[TN / 2];
            #pragma unroll
            for (int j = 0; j < TN / 2; j++)
                rb[j] = *(const unsigned long long*)&Bs[kk][tx * TN + 2 * j];
            #pragma unroll
            for (int i = 0; i < 8; i++) {
                unsigned long long ap = pack2(As[kk][ty * 8 + i]);
                #pragma unroll
                for (int j = 0; j < TN / 2; j++) ffma2(acc[i][j], ap, rb[j]);
            }
        }
        __syncthreads();
    }

    #pragma unroll
    for (int i = 0; i < 8; i++) {
        int r = rowA + ty * 8 + i;
        if (r < M) {
            float out[TN];
            #pragma unroll
            for (int j = 0; j < TN / 2; j++) unpack2(acc[i][j], out[2 * j], out[2 * j + 1]);
            #pragma unroll
            for (int q = 0; q < TN / 4; q++)
                *(float4*)&C[(size_t)r * Nc + colB + tx * TN + q * 4] =
                    make_float4(out[q * 4], out[q * 4 + 1], out[q * 4 + 2], out[q * 4 + 3]);
        }
    }
}

// ---------------- attention dot products -------------------------------------
__global__ void att1_kernel(const float* __restrict__ att_src, const float* __restrict__ att_dst) {
    int idx = blockIdx.x * blockDim.x + threadIdx.x;
    if (idx >= N_NODES * HEADS) return;
    int n = idx >> 3, h = idx & 7;
    const float4* hp = (const float4*)(g_h1 + (size_t)n * F1 + h * HID);
    const float4* as = (const float4*)(att_src + h * HID);
    const float4* ad = (const float4*)(att_dst + h * HID);
    float s = 0.f, d = 0.f;
    #pragma unroll
    for (int i = 0; i < 8; i++) {
        float4 hv = hp[i], a = as[i], b = ad[i];
        s += hv.x * a.x + hv.y * a.y + hv.z * a.z + hv.w * a.w;
        d += hv.x * b.x + hv.y * b.y + hv.z * b.z + hv.w * b.w;
    }
    g_asrc1[idx] = s;
    g_adst1[idx] = d;
}

__global__ void att2_kernel(const float* __restrict__ att_src, const float* __restrict__ att_dst) {
    int n = blockIdx.x * blockDim.x + threadIdx.x;
    if (n >= N_NODES) return;
    const float4* hp = (const float4*)(g_h2 + (size_t)n * OUT_C);
    const float4* as = (const float4*)att_src;
    const float4* ad = (const float4*)att_dst;
    float s = 0.f, d = 0.f;
    #pragma unroll
    for (int i = 0; i < 16; i++) {
        float4 hv = hp[i], a = as[i], b = ad[i];
        s += hv.x * a.x + hv.y * a.y + hv.z * a.z + hv.w * a.w;
        d += hv.x * b.x + hv.y * b.y + hv.z * b.z + hv.w * b.w;
    }
    g_asrc2[n] = s;
    g_adst2[n] = d;
}

// ---------------- layer-1 edge softmax (exp + denominator) -------------------
__global__ void edge_soft1(const int* __restrict__ ei) {
    int e = blockIdx.x * blockDim.x + threadIdx.x;
    if (e >= ETOT) return;
    int s, d;
    if (e < NUM_E) { s = ei[e]; d = ei[NUM_E + e]; } else { s = d = e - NUM_E; }
    const float4* ap = (const float4*)(g_asrc1 + (size_t)s * HEADS);
    const float4* bp = (const float4*)(g_adst1 + (size_t)d * HEADS);
    float4* exo = (float4*)(g_ex1 + (size_t)e * HEADS);
    float4 r[2];
    #pragma unroll
    for (int q = 0; q < 2; q++) {
        float4 a = ap[q], b = bp[q];
        r[q].x = __expf(lrelu(a.x + b.x));
        r[q].y = __expf(lrelu(a.y + b.y));
        r[q].z = __expf(lrelu(a.z + b.z));
        r[q].w = __expf(lrelu(a.w + b.w));
        exo[q] = r[q];
    }
    float* dp = g_den1 + (size_t)d * HEADS;
    red_add4(dp, r[0].x, r[0].y, r[0].z, r[0].w);
    red_add4(dp + 4, r[1].x, r[1].y, r[1].z, r[1].w);
}

// ---------------- layer-1 aggregation (warp per edge) ------------------------
__global__ __launch_bounds__(256) void edge_aggr1(const int* __restrict__ ei) {
    int e = blockIdx.x * (blockDim.x >> 5) + (threadIdx.x >> 5);
    if (e >= ETOT) return;
    int lane = threadIdx.x & 31;
    int s, d;
    if (e < NUM_E) { s = ei[e]; d = ei[NUM_E + e]; } else { s = d = e - NUM_E; }
    int head = lane >> 2;                      // lane covers elems [lane*8, lane*8+8) -> one head
    float a = g_ex1[(size_t)e * HEADS + head] / (g_den1[(size_t)d * HEADS + head] + EPS_F);
    const float4* hp = (const float4*)(g_h1 + (size_t)s * F1) + lane * 2;
    float4 v0 = hp[0], v1 = hp[1];
    float* op = g_out1 + (size_t)d * F1 + lane * 8;
    red_add4(op,     v0.x * a, v0.y * a, v0.z * a, v0.w * a);
    red_add4(op + 4, v1.x * a, v1.y * a, v1.z * a, v1.w * a);
}

// ---------------- layer-2 edge softmax ---------------------------------------
__global__ void edge_soft2(const int* __restrict__ ei) {
    int e = blockIdx.x * blockDim.x + threadIdx.x;
    if (e >= ETOT) return;
    int s, d;
    if (e < NUM_E) { s = ei[e]; d = ei[NUM_E + e]; } else { s = d = e - NUM_E; }
    float ex = __expf(lrelu(g_asrc2[s] + g_adst2[d]));
    g_ex2[e] = ex;
    atomicAdd(g_den2 + d, ex);
}

// ---------------- layer-2 aggregation (warp per edge, writes embeddings) -----
__global__ __launch_bounds__(256) void edge_aggr2(const int* __restrict__ ei, float* __restrict__ emb) {
    int e = blockIdx.x * (blockDim.x >> 5) + (threadIdx.x >> 5);
    if (e >= ETOT) return;
    int lane = threadIdx.x & 31;
    int s, d;
    if (e < NUM_E) { s = ei[e]; d = ei[NUM_E + e]; } else { s = d = e - NUM_E; }
    float a = g_ex2[e] / (g_den2[d] + EPS_F);
    float2 v = *(const float2*)(g_h2 + (size_t)s * OUT_C + lane * 2);
    red_add2(emb + (size_t)d * OUT_C + lane * 2, v.x * a, v.y * a);
}

// ---------------- fused MLP head + softmax -----------------------------------
__global__ __launch_bounds__(256) void mlp_kernel(
    const float* __restrict__ emb,
    const float* __restrict__ Wm1, const float* __restrict__ bm1,
    const float* __restrict__ Wm2, const float* __restrict__ bm2,
    float* __restrict__ s_out)
{
    __shared__ float sW1[OUT_C * 128];   // 32 KB
    __shared__ float sW2[128 * K_CL];    // 8 KB
    __shared__ float sb1[128];
    __shared__ float sb2[K_CL];
    __shared__ float sHid[8][128];
    __shared__ float sEmb[8][OUT_C];
    int tid = threadIdx.x;
    for (int i = tid; i < OUT_C * 128; i += 256) sW1[i] = Wm1[i];
    for (int i = tid; i < 128 * K_CL; i += 256) sW2[i] = Wm2[i];
    if (tid < 128) sb1[tid] = bm1[tid];
    if (tid < K_CL) sb2[tid] = bm2[tid];
    __syncthreads();
    int warp = tid >> 5, lane = tid & 31;
    int n = blockIdx.x * 8 + warp;
    if (n >= N_NODES) return;
    float2 e2 = *(const float2*)(emb + (size_t)n * OUT_C + lane * 2);
    sEmb[warp][lane * 2] = e2.x;
    sEmb[warp][lane * 2 + 1] = e2.y;
    __syncwarp();
    #pragma unroll
    for (int w = 0; w < 4; w++) {
        int j = lane + w * 32;
        float acc = sb1[j];
        #pragma unroll 8
        for (int c = 0; c < OUT_C; c++) acc += sEmb[warp][c] * sW1[c * 128 + j];
        sHid[warp][j] = fmaxf(acc, 0.f);
    }
    __syncwarp();
    if (lane < K_CL) {
        float lg = sb2[lane];
        #pragma unroll 16
        for (int k = 0; k < 128; k++) lg += sHid[warp][k] * sW2[k * K_CL + lane];
        float mx = lg;
        #pragma unroll
        for (int m = 8; m >= 1; m >>= 1)
            mx = fmaxf(mx, __shfl_xor_sync(0xffff, mx, m, 16));
        float ev = __expf(lg - mx);
        float sum = ev;
        #pragma unroll
        for (int m = 8; m >= 1; m >>= 1)
            sum += __shfl_xor_sync(0xffff, sum, m, 16);
        s_out[(size_t)n * K_CL + lane] = ev / sum;
    }
}

// ---------------- launch ------------------------------------------------------
extern "C" void kernel_launch(void* const* d_in, const int* in_sizes, int n_in,
                              void* d_out, int out_size) {
    const float* x        = (const float*)d_in[0];
    const int*   ei       = (const int*)d_in[1];     // [2, E]: src then dst
    const float* W1       = (const float*)d_in[2];
    const float* att_src1 = (const float*)d_in[3];
    const float* att_dst1 = (const float*)d_in[4];
    const float* b1       = (const float*)d_in[5];
    const float* W2       = (const float*)d_in[6];
    const float* att_src2 = (const float*)d_in[7];
    const float* att_dst2 = (const float*)d_in[8];
    const float* b2       = (const float*)d_in[9];
    const float* Wm1      = (const float*)d_in[10];
    const float* bm1      = (const float*)d_in[11];
    const float* Wm2      = (const float*)d_in[12];
    const float* bm2      = (const float*)d_in[13];

    float* s_out = (float*)d_out;                      // [N, 16]
    float* emb   = (float*)d_out + (size_t)N_NODES * K_CL;  // [N, 64]

    float *ph1, *pout1, *ph2;
    cudaGetSymbolAddress((void**)&ph1, g_h1);
    cudaGetSymbolAddress((void**)&pout1, g_out1);
    cudaGetSymbolAddress((void**)&ph2, g_h2);

    // 0. init accumulators (biases folded in)
    init_scratch<<<4096, 256>>>(emb, b1, b2);

    // 1. h1 = x @ W1   [50000,128]x[128,256]
    {
        dim3 grid(F1 / 128, (N_NODES + BMg - 1) / BMg);
        sgemm_f32x2<128, 8, false><<<grid, 256>>>(x, W1, ph1, N_NODES, F1, IN_C);
    }
    // 2. attention dots layer 1
    att1_kernel<<<(N_NODES * HEADS + 255) / 256, 256>>>(att_src1, att_dst1);
    // 3. edge softmax layer 1
    edge_soft1<<<(ETOT + 255) / 256, 256>>>(ei);
    // 4. edge aggregation layer 1 (warp/edge) — accumulates onto b1 init
    edge_aggr1<<<(ETOT + 7) / 8, 256>>>(ei);
    // 5. h2 = ELU(out1) @ W2  [50000,256]x[256,64]  (ELU fused into A-load)
    {
        dim3 grid(OUT_C / 64, (N_NODES + BMg - 1) / BMg);
        sgemm_f32x2<64, 4, true><<<grid, 256>>>(pout1, W2, ph2, N_NODES, OUT_C, F1);
    }
    // 6. attention dots layer 2
    att2_kernel<<<(N_NODES + 255) / 256, 256>>>(att_src2, att_dst2);
    // 7. edge softmax layer 2
    edge_soft2<<<(ETOT + 255) / 256, 256>>>(ei);
    // 8. edge aggregation layer 2 -> embeddings (accumulates onto b2 init)
    edge_aggr2<<<(ETOT + 7) / 8, 256>>>(ei, emb);
    // 9. MLP head + softmax -> s
    mlp_kernel<<<(N_NODES + 7) / 8, 256>>>(emb, Wm1, bm1, Wm2, bm2, s_out);
}

// round 5
// speedup vs baseline: 1.4815x; 1.3331x over previous
#include <cuda_runtime.h>
#include <math.h>

#define N_NODES 50000
#define NUM_E   400000
#define ETOT    (NUM_E + N_NODES)   // 450000, self-loops appended
#define IN_C    128
#define HID     32
#define HEADS   8
#define F1      (HEADS * HID)       // 256
#define OUT_C   64
#define K_CL    16
#define NEG_SLOPE 0.2f
#define EPS_F   1e-16f

// ---------------- scratch (device globals; no runtime allocation) -----------
__device__ float g_h1[(size_t)N_NODES * F1];     // x@W1
__device__ float g_out1[(size_t)N_NODES * F1];   // layer1 output (incl. b1)
__device__ float g_h2[(size_t)N_NODES * OUT_C];  // ELU(out1)@W2
__device__ float g_asrc1[N_NODES * HEADS];
__device__ float g_adst1[N_NODES * HEADS];
__device__ float g_asrc2[N_NODES];
__device__ float g_adst2[N_NODES];
// CSR by destination
__device__ int g_deg[N_NODES];
__device__ int g_start[N_NODES + 1];
__device__ int g_cursor[N_NODES];
__device__ int g_csr_src[ETOT];
__device__ int g_bsum[256];

// ---------------- helpers ----------------------------------------------------
__device__ __forceinline__ float lrelu(float x) { return x > 0.f ? x : NEG_SLOPE * x; }
__device__ __forceinline__ float elu1(float x)  { return x > 0.f ? x : expm1f(x); }

// packed f32x2 FMA (sm_103a FFMA2)
__device__ __forceinline__ void ffma2(unsigned long long& acc, unsigned long long a, unsigned long long b) {
    asm("fma.rn.f32x2 %0, %1, %2, %0;" : "+l"(acc) : "l"(a), "l"(b));
}
__device__ __forceinline__ unsigned long long pack2(float x) {
    unsigned long long r; asm("mov.b64 %0, {%1, %1};" : "=l"(r) : "f"(x)); return r;
}
__device__ __forceinline__ void unpack2(unsigned long long v, float& lo, float& hi) {
    asm("mov.b64 {%0, %1}, %2;" : "=f"(lo), "=f"(hi) : "l"(v));
}

// ---------------- CSR build ---------------------------------------------------
__global__ void zero_deg() {
    int i = blockIdx.x * blockDim.x + threadIdx.x;
    if (i < N_NODES) g_deg[i] = 0;
}
__global__ void hist_kernel(const int* __restrict__ ei) {
    int e = blockIdx.x * blockDim.x + threadIdx.x;
    if (e >= ETOT) return;
    int d = (e < NUM_E) ? ei[NUM_E + e] : e - NUM_E;
    atomicAdd(&g_deg[d], 1);
}
__global__ void scan1_kernel() {
    __shared__ int sm[256];
    int tid = threadIdx.x;
    int i = blockIdx.x * 256 + tid;
    int v = (i < N_NODES) ? g_deg[i] : 0;
    sm[tid] = v;
    __syncthreads();
    #pragma unroll
    for (int off = 1; off < 256; off <<= 1) {
        int t = (tid >= off) ? sm[tid - off] : 0;
        __syncthreads();
        sm[tid] += t;
        __syncthreads();
    }
    if (i < N_NODES) g_start[i] = sm[tid] - v;   // exclusive
    if (tid == 255) g_bsum[blockIdx.x] = sm[255];
}
__global__ void scan2_kernel(int nblocks) {
    __shared__ int sm[256];
    int tid = threadIdx.x;
    int v = (tid < nblocks) ? g_bsum[tid] : 0;
    sm[tid] = v;
    __syncthreads();
    #pragma unroll
    for (int off = 1; off < 256; off <<= 1) {
        int t = (tid >= off) ? sm[tid - off] : 0;
        __syncthreads();
        sm[tid] += t;
        __syncthreads();
    }
    if (tid < nblocks) g_bsum[tid] = sm[tid] - v;  // exclusive
}
__global__ void scan3_kernel() {
    int tid = threadIdx.x;
    int i = blockIdx.x * 256 + tid;
    if (i < N_NODES) {
        int s = g_start[i] + g_bsum[blockIdx.x];
        g_start[i] = s;
        g_cursor[i] = s;
    }
    if (i == 0) g_start[N_NODES] = ETOT;
}
__global__ void scatter_kernel(const int* __restrict__ ei) {
    int e = blockIdx.x * blockDim.x + threadIdx.x;
    if (e >= ETOT) return;
    int s, d;
    if (e < NUM_E) { s = ei[e]; d = ei[NUM_E + e]; } else { s = d = e - NUM_E; }
    int pos = atomicAdd(&g_cursor[d], 1);
    g_csr_src[pos] = s;
}

// ---------------- f32x2 SGEMM: C[M,Nc] = act(A)[M,Kc] @ B[Kc,Nc] -------------
#define BMg 128
#define BKg 16
template<int BN, int TN, bool ELU_A>
__global__ __launch_bounds__(256) void sgemm_f32x2(
    const float* __restrict__ A, const float* __restrict__ B,
    float* __restrict__ C, int M, int Nc, int Kc)
{
    __shared__ float As[BKg][BMg + 4];
    __shared__ float Bs[BKg][BN + 4];
    const int tid = threadIdx.x;
    const int tx = tid & 15, ty = tid >> 4;
    const int rowA = blockIdx.y * BMg;
    const int colB = blockIdx.x * BN;

    unsigned long long acc[8][TN / 2];
    #pragma unroll
    for (int i = 0; i < 8; i++)
        #pragma unroll
        for (int j = 0; j < TN / 2; j++) acc[i][j] = 0ULL;

    const int arow = tid >> 1;            // 0..127
    const int akq  = (tid & 1) * 4;       // 0 or 4

    for (int k0 = 0; k0 < Kc; k0 += BKg) {
        #pragma unroll
        for (int half = 0; half < 2; half++) {
            int kof = akq + half * 8;
            float4 v = make_float4(0.f, 0.f, 0.f, 0.f);
            if (rowA + arow < M)
                v = *(const float4*)&A[(size_t)(rowA + arow) * Kc + k0 + kof];
            if (ELU_A) { v.x = elu1(v.x); v.y = elu1(v.y); v.z = elu1(v.z); v.w = elu1(v.w); }
            As[kof + 0][arow] = v.x;
            As[kof + 1][arow] = v.y;
            As[kof + 2][arow] = v.z;
            As[kof + 3][arow] = v.w;
        }
        if (BN == 128) {
            int bc = (tid & 31) * 4, br = tid >> 5;
            #pragma unroll
            for (int pass = 0; pass < 2; pass++) {
                int r = br + pass * 8;
                float4 v = *(const float4*)&B[(size_t)(k0 + r) * Nc + colB + bc];
                *(float4*)&Bs[r][bc] = v;
            }
        } else {                                         // BN == 64
            int bc = (tid & 15) * 4, br = tid >> 4;
            float4 v = *(const float4*)&B[(size_t)(k0 + br) * Nc + colB + bc];
            *(float4*)&Bs[br][bc] = v;
        }
        __syncthreads();

        #pragma unroll
        for (int kk = 0; kk < BKg; kk++) {
            unsigned long long rb[TN / 2];
            #pragma unroll
            for (int j = 0; j < TN / 2; j++)
                rb[j] = *(const unsigned long long*)&Bs[kk][tx * TN + 2 * j];
            #pragma unroll
            for (int i = 0; i < 8; i++) {
                unsigned long long ap = pack2(As[kk][ty * 8 + i]);
                #pragma unroll
                for (int j = 0; j < TN / 2; j++) ffma2(acc[i][j], ap, rb[j]);
            }
        }
        __syncthreads();
    }

    #pragma unroll
    for (int i = 0; i < 8; i++) {
        int r = rowA + ty * 8 + i;
        if (r < M) {
            float out[TN];
            #pragma unroll
            for (int j = 0; j < TN / 2; j++) unpack2(acc[i][j], out[2 * j], out[2 * j + 1]);
            #pragma unroll
            for (int q = 0; q < TN / 4; q++)
                *(float4*)&C[(size_t)r * Nc + colB + tx * TN + q * 4] =
                    make_float4(out[q * 4], out[q * 4 + 1], out[q * 4 + 2], out[q * 4 + 3]);
        }
    }
}

// ---------------- attention dot products -------------------------------------
__global__ void att1_kernel(const float* __restrict__ att_src, const float* __restrict__ att_dst) {
    int idx = blockIdx.x * blockDim.x + threadIdx.x;
    if (idx >= N_NODES * HEADS) return;
    int n = idx >> 3, h = idx & 7;
    const float4* hp = (const float4*)(g_h1 + (size_t)n * F1 + h * HID);
    const float4* as = (const float4*)(att_src + h * HID);
    const float4* ad = (const float4*)(att_dst + h * HID);
    float s = 0.f, d = 0.f;
    #pragma unroll
    for (int i = 0; i < 8; i++) {
        float4 hv = hp[i], a = as[i], b = ad[i];
        s += hv.x * a.x + hv.y * a.y + hv.z * a.z + hv.w * a.w;
        d += hv.x * b.x + hv.y * b.y + hv.z * b.z + hv.w * b.w;
    }
    g_asrc1[idx] = s;
    g_adst1[idx] = d;
}

__global__ void att2_kernel(const float* __restrict__ att_src, const float* __restrict__ att_dst) {
    int n = blockIdx.x * blockDim.x + threadIdx.x;
    if (n >= N_NODES) return;
    const float4* hp = (const float4*)(g_h2 + (size_t)n * OUT_C);
    const float4* as = (const float4*)att_src;
    const float4* ad = (const float4*)att_dst;
    float s = 0.f, d = 0.f;
    #pragma unroll
    for (int i = 0; i < 16; i++) {
        float4 hv = hp[i], a = as[i], b = ad[i];
        s += hv.x * a.x + hv.y * a.y + hv.z * a.z + hv.w * a.w;
        d += hv.x * b.x + hv.y * b.y + hv.z * b.z + hv.w * b.w;
    }
    g_asrc2[n] = s;
    g_adst2[n] = d;
}

// ---------------- GAT layer 1: fused softmax + aggregation (warp/node) -------
__global__ __launch_bounds__(256) void gat1_csr(const float* __restrict__ b1) {
    int warp = threadIdx.x >> 5, lane = threadIdx.x & 31;
    int n = blockIdx.x * 8 + warp;
    if (n >= N_NODES) return;
    int beg = g_start[n], end = g_start[n + 1];

    // pass 1: denominators for 8 heads; lane = (edge_group:2 | head:3)
    int h8 = lane & 7;
    int eg = lane >> 3;
    float adst_p1 = g_adst1[n * 8 + h8];
    float den = 0.f;
    for (int e0 = beg; e0 < end; e0 += 4) {
        int e = e0 + eg;
        if (e < end) {
            int s = g_csr_src[e];
            den += __expf(lrelu(g_asrc1[s * 8 + h8] + adst_p1));
        }
    }
    den += __shfl_xor_sync(0xffffffffu, den, 8);
    den += __shfl_xor_sync(0xffffffffu, den, 16);
    // lane h holds den of head (h&7); pass-2 lane needs head = lane>>2
    int head = lane >> 2;
    float inv = 1.f / (__shfl_sync(0xffffffffu, den, head) + EPS_F);
    float adst_h = g_adst1[n * 8 + head];

    // pass 2: accumulate alpha * h1[src] in registers (8 floats/lane)
    float4 a0 = ((const float4*)b1)[lane * 2];
    float4 a1 = ((const float4*)b1)[lane * 2 + 1];
    for (int e = beg; e < end; e++) {
        int s = g_csr_src[e];
        float alpha = __expf(lrelu(g_asrc1[s * 8 + head] + adst_h)) * inv;
        const float4* hp = (const float4*)(g_h1 + (size_t)s * F1) + lane * 2;
        float4 v0 = hp[0], v1 = hp[1];
        a0.x += alpha * v0.x; a0.y += alpha * v0.y; a0.z += alpha * v0.z; a0.w += alpha * v0.w;
        a1.x += alpha * v1.x; a1.y += alpha * v1.y; a1.z += alpha * v1.z; a1.w += alpha * v1.w;
    }
    float4* op = (float4*)(g_out1 + (size_t)n * F1) + lane * 2;
    op[0] = a0; op[1] = a1;
}

// ---------------- GAT layer 2: fused softmax + aggregation (warp/node) -------
__global__ __launch_bounds__(256) void gat2_csr(float* __restrict__ emb, const float* __restrict__ b2) {
    int warp = threadIdx.x >> 5, lane = threadIdx.x & 31;
    int n = blockIdx.x * 8 + warp;
    if (n >= N_NODES) return;
    int beg = g_start[n], end = g_start[n + 1];
    float adst = g_adst2[n];

    float den = 0.f;
    for (int e = beg + lane; e < end; e += 32)
        den += __expf(lrelu(g_asrc2[g_csr_src[e]] + adst));
    #pragma unroll
    for (int m = 16; m >= 1; m >>= 1) den += __shfl_xor_sync(0xffffffffu, den, m);
    float inv = 1.f / (den + EPS_F);

    float2 acc = *(const float2*)(b2 + lane * 2);
    for (int e = beg; e < end; e++) {
        int s = g_csr_src[e];
        float alpha = __expf(lrelu(g_asrc2[s] + adst)) * inv;
        float2 v = *(const float2*)(g_h2 + (size_t)s * OUT_C + lane * 2);
        acc.x += alpha * v.x;
        acc.y += alpha * v.y;
    }
    *(float2*)(emb + (size_t)n * OUT_C + lane * 2) = acc;
}

// ---------------- fused MLP head + softmax (32 nodes/block) ------------------
__global__ __launch_bounds__(256) void mlp_kernel(
    const float* __restrict__ emb,
    const float* __restrict__ Wm1, const float* __restrict__ bm1,
    const float* __restrict__ Wm2, const float* __restrict__ bm2,
    float* __restrict__ s_out)
{
    __shared__ float sW1[OUT_C * 128];   // 32 KB
    __shared__ float sW2[128 * K_CL];    // 8 KB
    __shared__ float sb1[128];
    __shared__ float sb2[K_CL];
    __shared__ float sHid[8][128];
    __shared__ float sEmb[8][OUT_C];
    int tid = threadIdx.x;
    for (int i = tid; i < OUT_C * 128; i += 256) sW1[i] = Wm1[i];
    for (int i = tid; i < 128 * K_CL; i += 256) sW2[i] = Wm2[i];
    if (tid < 128) sb1[tid] = bm1[tid];
    if (tid < K_CL) sb2[tid] = bm2[tid];
    __syncthreads();
    int warp = tid >> 5, lane = tid & 31;
    #pragma unroll
    for (int it = 0; it < 4; it++) {
        int n = blockIdx.x * 32 + it * 8 + warp;
        if (n >= N_NODES) continue;
        float2 e2 = *(const float2*)(emb + (size_t)n * OUT_C + lane * 2);
        sEmb[warp][lane * 2] = e2.x;
        sEmb[warp][lane * 2 + 1] = e2.y;
        __syncwarp();
        #pragma unroll
        for (int w = 0; w < 4; w++) {
            int j = lane + w * 32;
            float acc = sb1[j];
            #pragma unroll 8
            for (int c = 0; c < OUT_C; c++) acc += sEmb[warp][c] * sW1[c * 128 + j];
            sHid[warp][j] = fmaxf(acc, 0.f);
        }
        __syncwarp();
        if (lane < K_CL) {
            float lg = sb2[lane];
            #pragma unroll 16
            for (int k = 0; k < 128; k++) lg += sHid[warp][k] * sW2[k * K_CL + lane];
            float mx = lg;
            #pragma unroll
            for (int m = 8; m >= 1; m >>= 1)
                mx = fmaxf(mx, __shfl_xor_sync(0xffff, mx, m, 16));
            float ev = __expf(lg - mx);
            float sum = ev;
            #pragma unroll
            for (int m = 8; m >= 1; m >>= 1)
                sum += __shfl_xor_sync(0xffff, sum, m, 16);
            s_out[(size_t)n * K_CL + lane] = ev / sum;
        }
        __syncwarp();
    }
}

// ---------------- launch ------------------------------------------------------
extern "C" void kernel_launch(void* const* d_in, const int* in_sizes, int n_in,
                              void* d_out, int out_size) {
    const float* x        = (const float*)d_in[0];
    const int*   ei       = (const int*)d_in[1];     // [2, E]: src then dst
    const float* W1       = (const float*)d_in[2];
    const float* att_src1 = (const float*)d_in[3];
    const float* att_dst1 = (const float*)d_in[4];
    const float* b1       = (const float*)d_in[5];
    const float* W2       = (const float*)d_in[6];
    const float* att_src2 = (const float*)d_in[7];
    const float* att_dst2 = (const float*)d_in[8];
    const float* b2       = (const float*)d_in[9];
    const float* Wm1      = (const float*)d_in[10];
    const float* bm1      = (const float*)d_in[11];
    const float* Wm2      = (const float*)d_in[12];
    const float* bm2      = (const float*)d_in[13];

    float* s_out = (float*)d_out;                           // [N, 16]
    float* emb   = (float*)d_out + (size_t)N_NODES * K_CL;  // [N, 64]

    float *ph1, *pout1, *ph2;
    cudaGetSymbolAddress((void**)&ph1, g_h1);
    cudaGetSymbolAddress((void**)&pout1, g_out1);
    cudaGetSymbolAddress((void**)&ph2, g_h2);

    const int NSCAN = (N_NODES + 255) / 256;   // 196

    // A. CSR build (by destination; shared by both GAT layers)
    zero_deg<<<NSCAN, 256>>>();
    hist_kernel<<<(ETOT + 255) / 256, 256>>>(ei);
    scan1_kernel<<<NSCAN, 256>>>();
    scan2_kernel<<<1, 256>>>(NSCAN);
    scan3_kernel<<<NSCAN, 256>>>();
    scatter_kernel<<<(ETOT + 255) / 256, 256>>>(ei);

    // B. h1 = x @ W1   [50000,128]x[128,256]
    {
        dim3 grid(F1 / 128, (N_NODES + BMg - 1) / BMg);
        sgemm_f32x2<128, 8, false><<<grid, 256>>>(x, W1, ph1, N_NODES, F1, IN_C);
    }
    // C. attention dots layer 1
    att1_kernel<<<(N_NODES * HEADS + 255) / 256, 256>>>(att_src1, att_dst1);
    // D. GAT layer 1 fused softmax+aggregation (b1 folded)
    gat1_csr<<<(N_NODES + 7) / 8, 256>>>(b1);
    // E. h2 = ELU(out1) @ W2  [50000,256]x[256,64]  (ELU fused into A-load)
    {
        dim3 grid(OUT_C / 64, (N_NODES + BMg - 1) / BMg);
        sgemm_f32x2<64, 4, true><<<grid, 256>>>(pout1, W2, ph2, N_NODES, OUT_C, F1);
    }
    // F. attention dots layer 2
    att2_kernel<<<(N_NODES + 255) / 256, 256>>>(att_src2, att_dst2);
    // G. GAT layer 2 fused -> embeddings (b2 folded)
    gat2_csr<<<(N_NODES + 7) / 8, 256>>>(emb, b2);
    // H. MLP head + softmax -> s
    mlp_kernel<<<(N_NODES + 31) / 32, 256>>>(emb, Wm1, bm1, Wm2, bm2, s_out);
}

// round 6
// speedup vs baseline: 1.6801x; 1.1340x over previous
#include <cuda_runtime.h>
#include <math.h>

#define N_NODES 50000
#define NUM_E   400000
#define ETOT    (NUM_E + N_NODES)   // 450000, self-loops appended
#define IN_C    128
#define HID     32
#define HEADS   8
#define F1      (HEADS * HID)       // 256
#define OUT_C   64
#define K_CL    16
#define NEG_SLOPE 0.2f
#define EPS_F   1e-16f

// ---------------- scratch (device globals; no runtime allocation) -----------
__device__ float g_h1[(size_t)N_NODES * F1];     // x@W1
__device__ float g_out1[(size_t)N_NODES * F1];   // layer1 output (incl. b1)
__device__ float g_h2[(size_t)N_NODES * OUT_C];  // ELU(out1)@W2
__device__ float g_asrc1[N_NODES * HEADS];
__device__ float g_adst1[N_NODES * HEADS];
__device__ float g_asrc2[N_NODES];
__device__ float g_adst2[N_NODES];
// CSR by destination
__device__ int g_deg[N_NODES];
__device__ int g_start[N_NODES + 1];
__device__ int g_cursor[N_NODES];
__device__ int g_csr_src[ETOT];
__device__ int g_bsum[256];
// pre-split weights (packed bf16x2 along k-pairs): [K/2][N]
__device__ unsigned g_w1hi[(IN_C / 2) * F1];
__device__ unsigned g_w1lo[(IN_C / 2) * F1];
__device__ unsigned g_w2hi[(F1 / 2) * OUT_C];
__device__ unsigned g_w2lo[(F1 / 2) * OUT_C];

// ---------------- helpers ----------------------------------------------------
__device__ __forceinline__ float lrelu(float x) { return x > 0.f ? x : NEG_SLOPE * x; }
__device__ __forceinline__ float elu1(float x)  { return x > 0.f ? x : expm1f(x); }

// pack two floats to bf16x2: low half = f_even, high half = f_odd
__device__ __forceinline__ unsigned pack_bf16(float f_even, float f_odd) {
    unsigned r;
    asm("cvt.rn.satfinite.bf16x2.f32 %0, %1, %2;" : "=r"(r) : "f"(f_odd), "f"(f_even));
    return r;
}
// split (f0,f1) into hi + lo bf16x2 pairs (3-product compensation scheme)
__device__ __forceinline__ void bf16_split(float f0, float f1, unsigned& hi, unsigned& lo) {
    hi = pack_bf16(f0, f1);
    float b0 = __uint_as_float(hi << 16);
    float b1 = __uint_as_float(hi & 0xffff0000u);
    lo = pack_bf16(f0 - b0, f1 - b1);
}

#define MMA_BF16(d, a, b0_, b1_) \
    asm("mma.sync.aligned.m16n8k16.row.col.f32.bf16.bf16.f32 " \
        "{%0,%1,%2,%3}, {%4,%5,%6,%7}, {%8,%9}, {%0,%1,%2,%3};" \
        : "+f"(d[0]), "+f"(d[1]), "+f"(d[2]), "+f"(d[3]) \
        : "r"(a[0]), "r"(a[1]), "r"(a[2]), "r"(a[3]), "r"(b0_), "r"(b1_))

// ---------------- weight split kernel ----------------------------------------
__global__ void split_w(const float* __restrict__ W, unsigned* __restrict__ hi,
                        unsigned* __restrict__ lo, int Kc, int Nc) {
    int i = blockIdx.x * blockDim.x + threadIdx.x;
    if (i >= (Kc / 2) * Nc) return;
    int kp = i / Nc, n = i - kp * Nc;
    float f0 = W[(size_t)(2 * kp) * Nc + n];
    float f1 = W[(size_t)(2 * kp + 1) * Nc + n];
    unsigned h, l;
    bf16_split(f0, f1, h, l);
    hi[i] = h;
    lo[i] = l;
}

// ---------------- CSR build ---------------------------------------------------
__global__ void zero_deg() {
    int i = blockIdx.x * blockDim.x + threadIdx.x;
    if (i < N_NODES) g_deg[i] = 0;
}
__global__ void hist_kernel(const int* __restrict__ ei) {
    int e = blockIdx.x * blockDim.x + threadIdx.x;
    if (e >= ETOT) return;
    int d = (e < NUM_E) ? ei[NUM_E + e] : e - NUM_E;
    atomicAdd(&g_deg[d], 1);
}
__global__ void scan1_kernel() {
    __shared__ int sm[256];
    int tid = threadIdx.x;
    int i = blockIdx.x * 256 + tid;
    int v = (i < N_NODES) ? g_deg[i] : 0;
    sm[tid] = v;
    __syncthreads();
    #pragma unroll
    for (int off = 1; off < 256; off <<= 1) {
        int t = (tid >= off) ? sm[tid - off] : 0;
        __syncthreads();
        sm[tid] += t;
        __syncthreads();
    }
    if (i < N_NODES) g_start[i] = sm[tid] - v;   // exclusive
    if (tid == 255) g_bsum[blockIdx.x] = sm[255];
}
__global__ void scan2_kernel(int nblocks) {
    __shared__ int sm[256];
    int tid = threadIdx.x;
    int v = (tid < nblocks) ? g_bsum[tid] : 0;
    sm[tid] = v;
    __syncthreads();
    #pragma unroll
    for (int off = 1; off < 256; off <<= 1) {
        int t = (tid >= off) ? sm[tid - off] : 0;
        __syncthreads();
        sm[tid] += t;
        __syncthreads();
    }
    if (tid < nblocks) g_bsum[tid] = sm[tid] - v;  // exclusive
}
__global__ void scan3_kernel() {
    int tid = threadIdx.x;
    int i = blockIdx.x * 256 + tid;
    if (i < N_NODES) {
        int s = g_start[i] + g_bsum[blockIdx.x];
        g_start[i] = s;
        g_cursor[i] = s;
    }
    if (i == 0) g_start[N_NODES] = ETOT;
}
__global__ void scatter_kernel(const int* __restrict__ ei) {
    int e = blockIdx.x * blockDim.x + threadIdx.x;
    if (e >= ETOT) return;
    int s, d;
    if (e < NUM_E) { s = ei[e]; d = ei[NUM_E + e]; } else { s = d = e - NUM_E; }
    int pos = atomicAdd(&g_cursor[d], 1);
    g_csr_src[pos] = s;
}

// ---------------- bf16 3-product tensor-core GEMM ----------------------------
// C[M,Nc] = act(A)[M,Kc] @ B[Kc,Nc];  B pre-split into hi/lo packed bf16x2.
// Block tile 128 x BN, k-tile 32 (two m16n8k16 steps), 256 threads (8 warps),
// warp grid 4(m) x 2(n), warp tile 32 x BN/2.
#define AS_STRIDE 20
template<int BN, bool ELU_A>
__global__ __launch_bounds__(256, 2) void gemm_bf16x3(
    const float* __restrict__ A,
    const unsigned* __restrict__ Bhi, const unsigned* __restrict__ Blo,
    float* __restrict__ C, int M, int Nc, int Kc)
{
    constexpr int NATOM = BN / 16;        // n-atoms per warp
    constexpr int BS_STRIDE = BN + 8;
    __shared__ unsigned sAhi[128 * AS_STRIDE];
    __shared__ unsigned sAlo[128 * AS_STRIDE];
    __shared__ unsigned sBhi[16 * BS_STRIDE];
    __shared__ unsigned sBlo[16 * BS_STRIDE];

    const int tid = threadIdx.x;
    const int warp = tid >> 5, lane = tid & 31;
    const int g = lane >> 2, tig = lane & 3;
    const int rowA = blockIdx.y * 128, colB = blockIdx.x * BN;
    const int wm = (warp >> 1) * 32, wn = (warp & 1) * (BN / 2);

    float d[2][NATOM][4];
    #pragma unroll
    for (int i = 0; i < 2; i++)
        #pragma unroll
        for (int j = 0; j < NATOM; j++)
            #pragma unroll
            for (int q = 0; q < 4; q++) d[i][j][q] = 0.f;

    const int arow = tid >> 1;               // 0..127
    const int ak0  = (tid & 1) * 16;         // fp32 k offset within k-tile
    const bool arow_ok = (rowA + arow) < M;
    const float* Aptr = A + (size_t)(rowA + arow) * Kc + ak0;

    const int bkp = tid >> 4;                // 0..15
    const int bn0 = (tid & 15) * (BN / 16);

    const int KT = Kc / 32;
    for (int kt = 0; kt < KT; kt++) {
        // ---- load & split A (fp32 -> bf16 hi/lo packed pairs) ----
        {
            float4 f[4];
            #pragma unroll
            for (int q = 0; q < 4; q++)
                f[q] = arow_ok ? *(const float4*)(Aptr + kt * 32 + q * 4)
                               : make_float4(0.f, 0.f, 0.f, 0.f);
            if (ELU_A) {
                #pragma unroll
                for (int q = 0; q < 4; q++) {
                    f[q].x = elu1(f[q].x); f[q].y = elu1(f[q].y);
                    f[q].z = elu1(f[q].z); f[q].w = elu1(f[q].w);
                }
            }
            unsigned* hp = sAhi + arow * AS_STRIDE + (ak0 >> 1);
            unsigned* lp = sAlo + arow * AS_STRIDE + (ak0 >> 1);
            #pragma unroll
            for (int q = 0; q < 4; q++) {
                unsigned h0, l0, h1, l1;
                bf16_split(f[q].x, f[q].y, h0, l0);
                bf16_split(f[q].z, f[q].w, h1, l1);
                hp[q * 2] = h0; hp[q * 2 + 1] = h1;
                lp[q * 2] = l0; lp[q * 2 + 1] = l1;
            }
        }
        // ---- load pre-split B tile ----
        {
            const unsigned* gh = Bhi + (size_t)(kt * 16 + bkp) * Nc + colB + bn0;
            const unsigned* gl = Blo + (size_t)(kt * 16 + bkp) * Nc + colB + bn0;
            unsigned* sh = sBhi + bkp * BS_STRIDE + bn0;
            unsigned* sl = sBlo + bkp * BS_STRIDE + bn0;
            #pragma unroll
            for (int q = 0; q < BN / 64; q++) {
                ((int4*)sh)[q] = ((const int4*)gh)[q];
                ((int4*)sl)[q] = ((const int4*)gl)[q];
            }
        }
        __syncthreads();

        // ---- two m16n8k16 steps ----
        #pragma unroll
        for (int s = 0; s < 2; s++) {
            const int kp = s * 8 + tig;
            unsigned ahi[2][4], alo[2][4];
            #pragma unroll
            for (int am = 0; am < 2; am++) {
                int m0 = wm + am * 16 + g;
                ahi[am][0] = sAhi[m0 * AS_STRIDE + kp];
                ahi[am][1] = sAhi[(m0 + 8) * AS_STRIDE + kp];
                ahi[am][2] = sAhi[m0 * AS_STRIDE + kp + 4];
                ahi[am][3] = sAhi[(m0 + 8) * AS_STRIDE + kp + 4];
                alo[am][0] = sAlo[m0 * AS_STRIDE + kp];
                alo[am][1] = sAlo[(m0 + 8) * AS_STRIDE + kp];
                alo[am][2] = sAlo[m0 * AS_STRIDE + kp + 4];
                alo[am][3] = sAlo[(m0 + 8) * AS_STRIDE + kp + 4];
            }
            #pragma unroll
            for (int an = 0; an < NATOM; an++) {
                int n = wn + an * 8 + g;
                unsigned bh0 = sBhi[kp * BS_STRIDE + n];
                unsigned bh1 = sBhi[(kp + 4) * BS_STRIDE + n];
                unsigned bl0 = sBlo[kp * BS_STRIDE + n];
                unsigned bl1 = sBlo[(kp + 4) * BS_STRIDE + n];
                #pragma unroll
                for (int am = 0; am < 2; am++) {
                    MMA_BF16(d[am][an], ahi[am], bh0, bh1);
                    MMA_BF16(d[am][an], alo[am], bh0, bh1);
                    MMA_BF16(d[am][an], ahi[am], bl0, bl1);
                }
            }
        }
        __syncthreads();
    }

    // ---- epilogue ----
    #pragma unroll
    for (int am = 0; am < 2; am++) {
        int r0 = rowA + wm + am * 16 + g;
        #pragma unroll
        for (int an = 0; an < NATOM; an++) {
            int c = colB + wn + an * 8 + 2 * tig;
            if (r0 < M)
                *(float2*)&C[(size_t)r0 * Nc + c] = make_float2(d[am][an][0], d[am][an][1]);
            if (r0 + 8 < M)
                *(float2*)&C[(size_t)(r0 + 8) * Nc + c] = make_float2(d[am][an][2], d[am][an][3]);
        }
    }
}

// ---------------- attention dot products -------------------------------------
__global__ void att1_kernel(const float* __restrict__ att_src, const float* __restrict__ att_dst) {
    int idx = blockIdx.x * blockDim.x + threadIdx.x;
    if (idx >= N_NODES * HEADS) return;
    int n = idx >> 3, h = idx & 7;
    const float4* hp = (const float4*)(g_h1 + (size_t)n * F1 + h * HID);
    const float4* as = (const float4*)(att_src + h * HID);
    const float4* ad = (const float4*)(att_dst + h * HID);
    float s = 0.f, d = 0.f;
    #pragma unroll
    for (int i = 0; i < 8; i++) {
        float4 hv = hp[i], a = as[i], b = ad[i];
        s += hv.x * a.x + hv.y * a.y + hv.z * a.z + hv.w * a.w;
        d += hv.x * b.x + hv.y * b.y + hv.z * b.z + hv.w * b.w;
    }
    g_asrc1[idx] = s;
    g_adst1[idx] = d;
}

__global__ void att2_kernel(const float* __restrict__ att_src, const float* __restrict__ att_dst) {
    int n = blockIdx.x * blockDim.x + threadIdx.x;
    if (n >= N_NODES) return;
    const float4* hp = (const float4*)(g_h2 + (size_t)n * OUT_C);
    const float4* as = (const float4*)att_src;
    const float4* ad = (const float4*)att_dst;
    float s = 0.f, d = 0.f;
    #pragma unroll
    for (int i = 0; i < 16; i++) {
        float4 hv = hp[i], a = as[i], b = ad[i];
        s += hv.x * a.x + hv.y * a.y + hv.z * a.z + hv.w * a.w;
        d += hv.x * b.x + hv.y * b.y + hv.z * b.z + hv.w * b.w;
    }
    g_asrc2[n] = s;
    g_adst2[n] = d;
}

// ---------------- GAT layer 1: fused softmax + aggregation (warp/node) -------
__global__ __launch_bounds__(256) void gat1_csr(const float* __restrict__ b1) {
    int warp = threadIdx.x >> 5, lane = threadIdx.x & 31;
    int n = blockIdx.x * 8 + warp;
    if (n >= N_NODES) return;
    int beg = g_start[n], end = g_start[n + 1];

    // pass 1: denominators for 8 heads; lane = (edge_group:2 | head:3)
    int h8 = lane & 7;
    int eg = lane >> 3;
    float adst_p1 = g_adst1[n * 8 + h8];
    float den = 0.f;
    for (int e0 = beg; e0 < end; e0 += 4) {
        int e = e0 + eg;
        if (e < end) {
            int s = g_csr_src[e];
            den += __expf(lrelu(g_asrc1[s * 8 + h8] + adst_p1));
        }
    }
    den += __shfl_xor_sync(0xffffffffu, den, 8);
    den += __shfl_xor_sync(0xffffffffu, den, 16);
    int head = lane >> 2;
    float inv = 1.f / (__shfl_sync(0xffffffffu, den, head) + EPS_F);
    float adst_h = g_adst1[n * 8 + head];

    // pass 2: accumulate alpha * h1[src] in registers (8 floats/lane)
    float4 a0 = ((const float4*)b1)[lane * 2];
    float4 a1 = ((const float4*)b1)[lane * 2 + 1];
    for (int e = beg; e < end; e++) {
        int s = g_csr_src[e];
        float alpha = __expf(lrelu(g_asrc1[s * 8 + head] + adst_h)) * inv;
        const float4* hp = (const float4*)(g_h1 + (size_t)s * F1) + lane * 2;
        float4 v0 = hp[0], v1 = hp[1];
        a0.x += alpha * v0.x; a0.y += alpha * v0.y; a0.z += alpha * v0.z; a0.w += alpha * v0.w;
        a1.x += alpha * v1.x; a1.y += alpha * v1.y; a1.z += alpha * v1.z; a1.w += alpha * v1.w;
    }
    float4* op = (float4*)(g_out1 + (size_t)n * F1) + lane * 2;
    op[0] = a0; op[1] = a1;
}

// ---------------- GAT layer 2: fused softmax + aggregation (warp/node) -------
__global__ __launch_bounds__(256) void gat2_csr(float* __restrict__ emb, const float* __restrict__ b2) {
    int warp = threadIdx.x >> 5, lane = threadIdx.x & 31;
    int n = blockIdx.x * 8 + warp;
    if (n >= N_NODES) return;
    int beg = g_start[n], end = g_start[n + 1];
    float adst = g_adst2[n];

    float den = 0.f;
    for (int e = beg + lane; e < end; e += 32)
        den += __expf(lrelu(g_asrc2[g_csr_src[e]] + adst));
    #pragma unroll
    for (int m = 16; m >= 1; m >>= 1) den += __shfl_xor_sync(0xffffffffu, den, m);
    float inv = 1.f / (den + EPS_F);

    float2 acc = *(const float2*)(b2 + lane * 2);
    for (int e = beg; e < end; e++) {
        int s = g_csr_src[e];
        float alpha = __expf(lrelu(g_asrc2[s] + adst)) * inv;
        float2 v = *(const float2*)(g_h2 + (size_t)s * OUT_C + lane * 2);
        acc.x += alpha * v.x;
        acc.y += alpha * v.y;
    }
    *(float2*)(emb + (size_t)n * OUT_C + lane * 2) = acc;
}

// ---------------- fused MLP head + softmax (32 nodes/block) ------------------
__global__ __launch_bounds__(256) void mlp_kernel(
    const float* __restrict__ emb,
    const float* __restrict__ Wm1, const float* __restrict__ bm1,
    const float* __restrict__ Wm2, const float* __restrict__ bm2,
    float* __restrict__ s_out)
{
    __shared__ float sW1[OUT_C * 128];   // 32 KB
    __shared__ float sW2[128 * K_CL];    // 8 KB
    __shared__ float sb1[128];
    __shared__ float sb2[K_CL];
    __shared__ float sHid[8][128];
    __shared__ float sEmb[8][OUT_C];
    int tid = threadIdx.x;
    for (int i = tid; i < OUT_C * 128; i += 256) sW1[i] = Wm1[i];
    for (int i = tid; i < 128 * K_CL; i += 256) sW2[i] = Wm2[i];
    if (tid < 128) sb1[tid] = bm1[tid];
    if (tid < K_CL) sb2[tid] = bm2[tid];
    __syncthreads();
    int warp = tid >> 5, lane = tid & 31;
    #pragma unroll
    for (int it = 0; it < 4; it++) {
        int n = blockIdx.x * 32 + it * 8 + warp;
        if (n >= N_NODES) continue;
        float2 e2 = *(const float2*)(emb + (size_t)n * OUT_C + lane * 2);
        sEmb[warp][lane * 2] = e2.x;
        sEmb[warp][lane * 2 + 1] = e2.y;
        __syncwarp();
        #pragma unroll
        for (int w = 0; w < 4; w++) {
            int j = lane + w * 32;
            float acc = sb1[j];
            #pragma unroll 8
            for (int c = 0; c < OUT_C; c++) acc += sEmb[warp][c] * sW1[c * 128 + j];
            sHid[warp][j] = fmaxf(acc, 0.f);
        }
        __syncwarp();
        if (lane < K_CL) {
            float lg = sb2[lane];
            #pragma unroll 16
            for (int k = 0; k < 128; k++) lg += sHid[warp][k] * sW2[k * K_CL + lane];
            float mx = lg;
            #pragma unroll
            for (int m = 8; m >= 1; m >>= 1)
                mx = fmaxf(mx, __shfl_xor_sync(0xffff, mx, m, 16));
            float ev = __expf(lg - mx);
            float sum = ev;
            #pragma unroll
            for (int m = 8; m >= 1; m >>= 1)
                sum += __shfl_xor_sync(0xffff, sum, m, 16);
            s_out[(size_t)n * K_CL + lane] = ev / sum;
        }
        __syncwarp();
    }
}

// ---------------- launch ------------------------------------------------------
extern "C" void kernel_launch(void* const* d_in, const int* in_sizes, int n_in,
                              void* d_out, int out_size) {
    const float* x        = (const float*)d_in[0];
    const int*   ei       = (const int*)d_in[1];     // [2, E]: src then dst
    const float* W1       = (const float*)d_in[2];
    const float* att_src1 = (const float*)d_in[3];
    const float* att_dst1 = (const float*)d_in[4];
    const float* b1       = (const float*)d_in[5];
    const float* W2       = (const float*)d_in[6];
    const float* att_src2 = (const float*)d_in[7];
    const float* att_dst2 = (const float*)d_in[8];
    const float* b2       = (const float*)d_in[9];
    const float* Wm1      = (const float*)d_in[10];
    const float* bm1      = (const float*)d_in[11];
    const float* Wm2      = (const float*)d_in[12];
    const float* bm2      = (const float*)d_in[13];

    float* s_out = (float*)d_out;                           // [N, 16]
    float* emb   = (float*)d_out + (size_t)N_NODES * K_CL;  // [N, 64]

    float *ph1, *pout1, *ph2;
    cudaGetSymbolAddress((void**)&ph1, g_h1);
    cudaGetSymbolAddress((void**)&pout1, g_out1);
    cudaGetSymbolAddress((void**)&ph2, g_h2);
    unsigned *pw1hi, *pw1lo, *pw2hi, *pw2lo;
    cudaGetSymbolAddress((void**)&pw1hi, g_w1hi);
    cudaGetSymbolAddress((void**)&pw1lo, g_w1lo);
    cudaGetSymbolAddress((void**)&pw2hi, g_w2hi);
    cudaGetSymbolAddress((void**)&pw2lo, g_w2lo);

    const int NSCAN = (N_NODES + 255) / 256;   // 196

    // A. weight splits (independent of everything else)
    split_w<<<(IN_C / 2 * F1 + 255) / 256, 256>>>(W1, pw1hi, pw1lo, IN_C, F1);
    split_w<<<(F1 / 2 * OUT_C + 255) / 256, 256>>>(W2, pw2hi, pw2lo, F1, OUT_C);

    // B. CSR build (by destination; shared by both GAT layers)
    zero_deg<<<NSCAN, 256>>>();
    hist_kernel<<<(ETOT + 255) / 256, 256>>>(ei);
    scan1_kernel<<<NSCAN, 256>>>();
    scan2_kernel<<<1, 256>>>(NSCAN);
    scan3_kernel<<<NSCAN, 256>>>();
    scatter_kernel<<<(ETOT + 255) / 256, 256>>>(ei);

    // C. h1 = x @ W1   [50000,128]x[128,256]  (bf16 3-product tensor cores)
    {
        dim3 grid(F1 / 128, (N_NODES + 127) / 128);
        gemm_bf16x3<128, false><<<grid, 256>>>(x, pw1hi, pw1lo, ph1, N_NODES, F1, IN_C);
    }
    // D. attention dots layer 1
    att1_kernel<<<(N_NODES * HEADS + 255) / 256, 256>>>(att_src1, att_dst1);
    // E. GAT layer 1 fused softmax+aggregation (b1 folded)
    gat1_csr<<<(N_NODES + 7) / 8, 256>>>(b1);
    // F. h2 = ELU(out1) @ W2  [50000,256]x[256,64]  (ELU fused into A-split)
    {
        dim3 grid(OUT_C / 64, (N_NODES + 127) / 128);
        gemm_bf16x3<64, true><<<grid, 256>>>(pout1, pw2hi, pw2lo, ph2, N_NODES, OUT_C, F1);
    }
    // G. attention dots layer 2
    att2_kernel<<<(N_NODES + 255) / 256, 256>>>(att_src2, att_dst2);
    // H. GAT layer 2 fused -> embeddings (b2 folded)
    gat2_csr<<<(N_NODES + 7) / 8, 256>>>(emb, b2);
    // I. MLP head + softmax -> s
    mlp_kernel<<<(N_NODES + 31) / 32, 256>>>(emb, Wm1, bm1, Wm2, bm2, s_out);
}